// round 4
// baseline (speedup 1.0000x reference)
#include <cuda_runtime.h>

#define Bsz 64
#define Dd  512
#define Ll  8192
#define NLn 1000

typedef unsigned long long ull;

// Intermediates (device globals; allocations forbidden).
// NOTE: never pass these as kernel arguments from host code — the host-side
// shadow symbol is not the device address. Kernels reference them directly.
__device__ __align__(16) float g_ye0 [Bsz*Dd];
__device__ __align__(16) float g_ye1 [Bsz*Dd];
__device__ __align__(16) float g_ye2 [Bsz*Dd];
__device__ __align__(16) float g_zz1 [Bsz*Dd];
__device__ __align__(16) float g_zz2 [Bsz*Dd];
__device__ __align__(16) float g_zz2T[Dd*Bsz];   // k-major for k_big
__device__ __align__(16) float g_s[Bsz];

__device__ __forceinline__ void cp_async16(void* dst, const void* src) {
    unsigned s = (unsigned)__cvta_generic_to_shared(dst);
    asm volatile("cp.async.cg.shared.global [%0], [%1], 16;" :: "r"(s), "l"(src) : "memory");
}
__device__ __forceinline__ ull pack2(float lo, float hi) {
    ull r; asm("mov.b64 %0, {%1, %2};" : "=l"(r) : "f"(lo), "f"(hi)); return r;
}
__device__ __forceinline__ void unpack2(float& lo, float& hi, ull v) {
    asm("mov.b64 {%0, %1}, %2;" : "=f"(lo), "=f"(hi) : "l"(v));
}
__device__ __forceinline__ void ffma2(ull& d, ull a, ull b) {
    asm("fma.rn.f32x2 %0, %1, %2, %0;" : "+l"(d) : "l"(a), "l"(b));
}
__device__ __forceinline__ ull fmul2(ull a, ull b) {
    ull r; asm("mul.rn.f32x2 %0, %1, %2;" : "=l"(r) : "l"(a), "l"(b)); return r;
}
__device__ __forceinline__ void red4(float* p, float v0, float v1, float v2, float v3) {
    asm volatile("red.global.add.v4.f32 [%0], {%1,%2,%3,%4};"
                 :: "l"(p), "f"(v0), "f"(v1), "f"(v2), "f"(v3) : "memory");
}

// ---------------------------------------------------------------------------
// K1: ye0 gather (row-major), residual inits for stage 1, zero stage-2 Cs.
// ---------------------------------------------------------------------------
__global__ void k_prep(const float* __restrict__ z, const int* __restrict__ y,
                       const float* __restrict__ W_yemb, const float* __restrict__ b_yemb,
                       const float* __restrict__ by1, const float* __restrict__ bz1) {
    int b = blockIdx.x, e = threadIdx.x;
    int yb = __ldg(y + b);
    float v  = W_yemb[e*NLn + yb] + b_yemb[e];
    float zv = z[b*Dd + e];
    g_ye0[b*Dd + e] = v;
    g_ye1[b*Dd + e] = v  + by1[e];
    g_zz1[b*Dd + e] = zv + bz1[e];
    g_ye2[b*Dd + e] = 0.f;
    g_zz2[b*Dd + e] = 0.f;
}

// ---------------------------------------------------------------------------
// Small residual GEMM: C += A @ W^T   (A row-major [64,512], W [512,512])
// CTA: 64b x 32e, k-chunk 64, split-K=8. grid(16*8, 2), 256 threads.
// Accumulator pairs over e (contiguous) -> red.global.add.v4.f32 epilogue.
// A read by broadcast LDS.32 (no transpose); W transposed in-smem (stride 32).
// STAGE==2: split-0 CTAs fold the residual init (A + b2) before the RED.
// A and C are device globals selected INSIDE the kernel (STAGE, blockIdx.y).
// ---------------------------------------------------------------------------
template<int STAGE>
__global__ void __launch_bounds__(256) k_small(const float* __restrict__ z,
                                               const float* __restrict__ Wy,
                                               const float* __restrict__ Wz,
                                               const float* __restrict__ b2y,
                                               const float* __restrict__ b2z) {
    __shared__ float sA[64*68];   // [b][k] pad 68 (conflict-free broadcast reads)
    __shared__ float sW[64*32];   // [k][e] transposed
    const float* A; const float* W; const float* b2; float* C;
    if (STAGE == 1) {
        if (blockIdx.y == 0) { A = g_ye0; W = Wy; b2 = nullptr; C = g_ye1; }
        else                 { A = z;     W = Wz; b2 = nullptr; C = g_zz1; }
    } else {
        if (blockIdx.y == 0) { A = g_ye1; W = Wy; b2 = b2y; C = g_ye2; }
        else                 { A = g_zz1; W = Wz; b2 = b2z; C = g_zz2; }
    }
    const int t  = threadIdx.x;
    const int e0 = (blockIdx.x & 15) * 32;
    const int k0 = (blockIdx.x >> 4) * 64;

    // A tile [64][64] via cp.async, row-major, stride 68
    #pragma unroll
    for (int r = 0; r < 4; r++) {
        int id = t + 256*r;              // 0..1023
        int b = id >> 4, k4 = id & 15;
        cp_async16(&sA[b*68 + 4*k4], A + b*Dd + k0 + 4*k4);
    }
    asm volatile("cp.async.commit_group;" ::: "memory");
    // W tile [32e][64k] -> sW[k][e] transpose via LDG + STS
    float4 wv[2]; int we[2], wk[2];
    #pragma unroll
    for (int r = 0; r < 2; r++) {
        int id = t + 256*r;              // 0..511
        we[r] = id >> 4; wk[r] = id & 15;
        wv[r] = *(const float4*)(W + (e0 + we[r])*Dd + k0 + 4*wk[r]);
    }
    #pragma unroll
    for (int r = 0; r < 2; r++) {
        sW[(4*wk[r] + 0)*32 + we[r]] = wv[r].x;
        sW[(4*wk[r] + 1)*32 + we[r]] = wv[r].y;
        sW[(4*wk[r] + 2)*32 + we[r]] = wv[r].z;
        sW[(4*wk[r] + 3)*32 + we[r]] = wv[r].w;
    }
    asm volatile("cp.async.wait_group 0;" ::: "memory");
    __syncthreads();

    const int b  = t >> 2;     // 0..63
    const int eg = t & 3;      // e-octet: e0 + eg*8 .. +7
    ull acc[4] = {0, 0, 0, 0};

    #pragma unroll 8
    for (int k = 0; k < 64; k++) {
        float a = sA[b*68 + k];
        ull ap = pack2(a, a);
        ulonglong2 wA = *(const ulonglong2*)&sW[k*32 + eg*8];
        ulonglong2 wB = *(const ulonglong2*)&sW[k*32 + eg*8 + 4];
        ffma2(acc[0], ap, wA.x);
        ffma2(acc[1], ap, wA.y);
        ffma2(acc[2], ap, wB.x);
        ffma2(acc[3], ap, wB.y);
    }

    float v[8];
    unpack2(v[0], v[1], acc[0]);
    unpack2(v[2], v[3], acc[1]);
    unpack2(v[4], v[5], acc[2]);
    unpack2(v[6], v[7], acc[3]);
    const int eo = e0 + eg*8;
    if (STAGE == 2 && k0 == 0) {
        // fold residual init: C starts at zero; add A + b2 once (this split only)
        float4 p0 = *(const float4*)&A[b*Dd + eo];
        float4 p1 = *(const float4*)&A[b*Dd + eo + 4];
        float4 q0 = *(const float4*)&b2[eo];
        float4 q1 = *(const float4*)&b2[eo + 4];
        v[0] += p0.x + q0.x; v[1] += p0.y + q0.y;
        v[2] += p0.z + q0.z; v[3] += p0.w + q0.w;
        v[4] += p1.x + q1.x; v[5] += p1.y + q1.y;
        v[6] += p1.z + q1.z; v[7] += p1.w + q1.w;
    }
    red4(&C[b*Dd + eo],     v[0], v[1], v[2], v[3]);
    red4(&C[b*Dd + eo + 4], v[4], v[5], v[6], v[7]);
}

// K4: s[b] = dot(ye2[b], w_proj); also transpose zz2 -> zz2T for k_big
__global__ void k_sproj(const float* __restrict__ w_proj) {
    int b = blockIdx.x, t = threadIdx.x;
    float p = 0.f;
    for (int e = t; e < Dd; e += 128) {
        float v = g_zz2[b*Dd + e];
        g_zz2T[e*Bsz + b] = v;
        p += g_ye2[b*Dd + e] * w_proj[e];
    }
    #pragma unroll
    for (int o = 16; o; o >>= 1) p += __shfl_down_sync(0xffffffffu, p, o);
    __shared__ float sm[4];
    if ((t & 31) == 0) sm[t >> 5] = p;
    __syncthreads();
    if (t == 0) g_s[b] = sm[0] + sm[1] + sm[2] + sm[3];
}

// ---------------------------------------------------------------------------
// K5: out[b,l] = s[b] * dot(zz2[b,:], W_zlat[l,:])
// CTA: 64b x 64l, 256 threads, thread 8b x 2l (8 FFMA2 accs).
// A (zz2T, k-major) via cp.async double-buffer; W via LDG->STS k-major
// transpose (stride 65, conflict-free both sides).
// ---------------------------------------------------------------------------
__global__ void __launch_bounds__(256) k_big(const float* __restrict__ Wz,
                                             float* __restrict__ out) {
    __shared__ float sA[2][32*64];   // [k][b]  8KB each (zz2T chunk, contiguous)
    __shared__ float sW[2][32*65];   // [k][l]  pad 65 -> conflict-free
    const int t  = threadIdx.x;
    const int l0 = blockIdx.x * 64;
    const int lc = t & 31;           // l = l0+lc, l0+32+lc
    const int bg = t >> 5;           // b = 4bg..4bg+3 and 32+4bg..+3

    auto loadA = [&](int buf, int c) {
        #pragma unroll
        for (int r = 0; r < 2; r++) {
            int id = t + 256*r;      // 0..511 f4
            cp_async16(&sA[buf][id*4], g_zz2T + c*32*Bsz + id*4);
        }
        asm volatile("cp.async.commit_group;" ::: "memory");
    };
    float4 wv[2];
    auto ldgW = [&](int c) {
        #pragma unroll
        for (int r = 0; r < 2; r++) {
            int id = t + 256*r;      // l = id>>3 (64), k4 = id&7 (8)
            wv[r] = *(const float4*)(Wz + (l0 + (id >> 3))*Dd + c*32 + 4*(id & 7));
        }
    };
    auto stsW = [&](int buf) {
        #pragma unroll
        for (int r = 0; r < 2; r++) {
            int id = t + 256*r;
            int l = id >> 3, k4 = id & 7;
            sW[buf][(4*k4 + 0)*65 + l] = wv[r].x;
            sW[buf][(4*k4 + 1)*65 + l] = wv[r].y;
            sW[buf][(4*k4 + 2)*65 + l] = wv[r].z;
            sW[buf][(4*k4 + 3)*65 + l] = wv[r].w;
        }
    };

    ull acc[4][2];
    #pragma unroll
    for (int i = 0; i < 4; i++) { acc[i][0] = 0; acc[i][1] = 0; }

    ldgW(0);
    loadA(0, 0);
    #pragma unroll 1
    for (int c = 0; c < 16; c++) {
        const int cur = c & 1;
        stsW(cur);
        asm volatile("cp.async.wait_group 0;" ::: "memory");
        __syncthreads();             // sA[cur] arrived, sW[cur] stored, prev buf free
        if (c < 16 - 1) {
            ldgW(c + 1);
            loadA(cur ^ 1, c + 1);
        }
        const float* Ab = sA[cur];
        const float* Wb = sW[cur];
        #pragma unroll 4
        for (int k = 0; k < 32; k++) {
            ulonglong2 a01 = *(const ulonglong2*)&Ab[k*Bsz + 4*bg];
            ulonglong2 a23 = *(const ulonglong2*)&Ab[k*Bsz + 32 + 4*bg];
            float w0 = Wb[k*65 + lc];
            float w1 = Wb[k*65 + 32 + lc];
            ull wp0 = pack2(w0, w0), wp1 = pack2(w1, w1);
            ffma2(acc[0][0], a01.x, wp0); ffma2(acc[1][0], a01.y, wp0);
            ffma2(acc[2][0], a23.x, wp0); ffma2(acc[3][0], a23.y, wp0);
            ffma2(acc[0][1], a01.x, wp1); ffma2(acc[1][1], a01.y, wp1);
            ffma2(acc[2][1], a23.x, wp1); ffma2(acc[3][1], a23.y, wp1);
        }
        __syncthreads();             // done reading cur before it is overwritten
    }

    // scale by s[b] and store
    float2 sl = *(const float2*)&g_s[4*bg];
    float2 sh = *(const float2*)&g_s[4*bg + 2];
    float2 tl = *(const float2*)&g_s[32 + 4*bg];
    float2 th = *(const float2*)&g_s[32 + 4*bg + 2];
    ull sp[4] = { pack2(sl.x, sl.y), pack2(sh.x, sh.y),
                  pack2(tl.x, tl.y), pack2(th.x, th.y) };
    int bb[4] = { 4*bg, 4*bg + 2, 32 + 4*bg, 32 + 4*bg + 2 };
    #pragma unroll
    for (int p = 0; p < 4; p++) {
        #pragma unroll
        for (int j = 0; j < 2; j++) {
            float lo, hi;
            unpack2(lo, hi, fmul2(acc[p][j], sp[p]));
            out[(bb[p] + 0)*Ll + l0 + 32*j + lc] = lo;
            out[(bb[p] + 1)*Ll + l0 + 32*j + lc] = hi;
        }
    }
}

extern "C" void kernel_launch(void* const* d_in, const int* in_sizes, int n_in,
                              void* d_out, int out_size) {
    const float* z      = (const float*)d_in[0];
    const int*   y      = (const int*)  d_in[1];
    const float* W_yemb = (const float*)d_in[2];
    const float* b_yemb = (const float*)d_in[3];
    const float* Wy1    = (const float*)d_in[4];
    const float* by1    = (const float*)d_in[5];
    const float* Wy2    = (const float*)d_in[6];
    const float* by2    = (const float*)d_in[7];
    const float* Wz1    = (const float*)d_in[8];
    const float* bz1    = (const float*)d_in[9];
    const float* Wz2    = (const float*)d_in[10];
    const float* bz2    = (const float*)d_in[11];
    const float* W_zlat = (const float*)d_in[12];
    const float* w_proj = (const float*)d_in[13];
    float* out = (float*)d_out;

    k_prep<<<Bsz, Dd>>>(z, y, W_yemb, b_yemb, by1, bz1);
    k_small<1><<<dim3(128, 2), 256>>>(z, Wy1, Wz1, nullptr, nullptr);
    k_small<2><<<dim3(128, 2), 256>>>(z, Wy2, Wz2, by2, bz2);
    k_sproj<<<Bsz, 128>>>(w_proj);
    k_big<<<Ll/64, 256>>>(W_zlat, out);
}

// round 5
// speedup vs baseline: 1.0972x; 1.0972x over previous
#include <cuda_runtime.h>

#define Bsz 64
#define Dd  512
#define Ll  8192
#define NLn 1000

typedef unsigned long long ull;

// Intermediates (device globals; allocations forbidden).
// Never passed as host-side kernel args — kernels reference them directly.
__device__ __align__(16) float g_ye0 [Bsz*Dd];
__device__ __align__(16) float g_ye1 [Bsz*Dd];
__device__ __align__(16) float g_ye2 [Bsz*Dd];
__device__ __align__(16) float g_zz1 [Bsz*Dd];
__device__ __align__(16) float g_zz2 [Bsz*Dd];
__device__ __align__(16) float g_s_pad[Bsz*32];   // s[b] at b*32 (sector-spread atomics)

__device__ __forceinline__ void cp_async16(void* dst, const void* src) {
    unsigned s = (unsigned)__cvta_generic_to_shared(dst);
    asm volatile("cp.async.cg.shared.global [%0], [%1], 16;" :: "r"(s), "l"(src) : "memory");
}
__device__ __forceinline__ ull pack2(float lo, float hi) {
    ull r; asm("mov.b64 %0, {%1, %2};" : "=l"(r) : "f"(lo), "f"(hi)); return r;
}
__device__ __forceinline__ void unpack2(float& lo, float& hi, ull v) {
    asm("mov.b64 {%0, %1}, %2;" : "=f"(lo), "=f"(hi) : "l"(v));
}
__device__ __forceinline__ void ffma2(ull& d, ull a, ull b) {
    asm("fma.rn.f32x2 %0, %1, %2, %0;" : "+l"(d) : "l"(a), "l"(b));
}
__device__ __forceinline__ ull fmul2(ull a, ull b) {
    ull r; asm("mul.rn.f32x2 %0, %1, %2;" : "=l"(r) : "l"(a), "l"(b)); return r;
}
__device__ __forceinline__ void red4(float* p, float v0, float v1, float v2, float v3) {
    asm volatile("red.global.add.v4.f32 [%0], {%1,%2,%3,%4};"
                 :: "l"(p), "f"(v0), "f"(v1), "f"(v2), "f"(v3) : "memory");
}

// ---------------------------------------------------------------------------
// K1: ye0 gather, stage-1 residual inits, zero stage-2 accumulators + s.
// grid (64 b, 4 e-quarters) x 128 threads -> 32K threads, gather MLP-rich.
// ---------------------------------------------------------------------------
__global__ void k_prep(const float* __restrict__ z, const int* __restrict__ y,
                       const float* __restrict__ W_yemb, const float* __restrict__ b_yemb,
                       const float* __restrict__ by1, const float* __restrict__ bz1) {
    int b = blockIdx.x;
    int e = blockIdx.y * 128 + threadIdx.x;
    int yb = __ldg(y + b);
    float v  = __ldg(W_yemb + e*NLn + yb) + b_yemb[e];
    float zv = z[b*Dd + e];
    g_ye0[b*Dd + e] = v;
    g_ye1[b*Dd + e] = v  + by1[e];
    g_zz1[b*Dd + e] = zv + bz1[e];
    g_ye2[b*Dd + e] = 0.f;
    g_zz2[b*Dd + e] = 0.f;
    if (blockIdx.y == 0 && threadIdx.x == 0) g_s_pad[b*32] = 0.f;
}

// ---------------------------------------------------------------------------
// Small residual GEMM: C += A @ W^T   (A row-major [64,512], W [512,512])
// CTA: 64b x 32e, k-chunk 64, split-K=8. grid(128, 2), 256 threads.
// e-paired FFMA2 accumulators -> red.global.add.v4.f32 epilogue.
// STAGE==2: split-0 folds residual init (A + b2); y-branch folds the
// w_proj dot into g_s_pad via shfl-reduced atomicAdd (kills k_sproj).
// ---------------------------------------------------------------------------
template<int STAGE>
__global__ void __launch_bounds__(256) k_small(const float* __restrict__ z,
                                               const float* __restrict__ Wy,
                                               const float* __restrict__ Wz,
                                               const float* __restrict__ b2y,
                                               const float* __restrict__ b2z,
                                               const float* __restrict__ w_proj) {
    __shared__ float sA[64*68];   // [b][k] pad 68 (broadcast-read conflict-free)
    __shared__ float sW[64*32];   // [k][e] transposed
    const float* A; const float* W; const float* b2; float* C;
    if (STAGE == 1) {
        if (blockIdx.y == 0) { A = g_ye0; W = Wy; b2 = nullptr; C = g_ye1; }
        else                 { A = z;     W = Wz; b2 = nullptr; C = g_zz1; }
    } else {
        if (blockIdx.y == 0) { A = g_ye1; W = Wy; b2 = b2y; C = g_ye2; }
        else                 { A = g_zz1; W = Wz; b2 = b2z; C = g_zz2; }
    }
    const int t  = threadIdx.x;
    const int e0 = (blockIdx.x & 15) * 32;
    const int k0 = (blockIdx.x >> 4) * 64;

    // A tile [64][64] via cp.async, row-major, stride 68
    #pragma unroll
    for (int r = 0; r < 4; r++) {
        int id = t + 256*r;              // 0..1023
        int b = id >> 4, k4 = id & 15;
        cp_async16(&sA[b*68 + 4*k4], A + b*Dd + k0 + 4*k4);
    }
    asm volatile("cp.async.commit_group;" ::: "memory");
    // W tile [32e][64k] -> sW[k][e] transpose via LDG + STS
    float4 wv[2]; int we[2], wk[2];
    #pragma unroll
    for (int r = 0; r < 2; r++) {
        int id = t + 256*r;              // 0..511
        we[r] = id >> 4; wk[r] = id & 15;
        wv[r] = *(const float4*)(W + (e0 + we[r])*Dd + k0 + 4*wk[r]);
    }
    #pragma unroll
    for (int r = 0; r < 2; r++) {
        sW[(4*wk[r] + 0)*32 + we[r]] = wv[r].x;
        sW[(4*wk[r] + 1)*32 + we[r]] = wv[r].y;
        sW[(4*wk[r] + 2)*32 + we[r]] = wv[r].z;
        sW[(4*wk[r] + 3)*32 + we[r]] = wv[r].w;
    }
    asm volatile("cp.async.wait_group 0;" ::: "memory");
    __syncthreads();

    const int b  = t >> 2;     // 0..63
    const int eg = t & 3;      // e-octet: e0 + eg*8 .. +7
    ull acc[4] = {0, 0, 0, 0};

    #pragma unroll 8
    for (int k = 0; k < 64; k++) {
        float a = sA[b*68 + k];
        ull ap = pack2(a, a);
        ulonglong2 wA = *(const ulonglong2*)&sW[k*32 + eg*8];
        ulonglong2 wB = *(const ulonglong2*)&sW[k*32 + eg*8 + 4];
        ffma2(acc[0], ap, wA.x);
        ffma2(acc[1], ap, wA.y);
        ffma2(acc[2], ap, wB.x);
        ffma2(acc[3], ap, wB.y);
    }

    float v[8];
    unpack2(v[0], v[1], acc[0]);
    unpack2(v[2], v[3], acc[1]);
    unpack2(v[4], v[5], acc[2]);
    unpack2(v[6], v[7], acc[3]);
    const int eo = e0 + eg*8;
    if (STAGE == 2 && k0 == 0) {
        // fold residual init: C starts at zero; add A + b2 once (this split only)
        float4 p0 = *(const float4*)&A[b*Dd + eo];
        float4 p1 = *(const float4*)&A[b*Dd + eo + 4];
        float4 q0 = *(const float4*)&b2[eo];
        float4 q1 = *(const float4*)&b2[eo + 4];
        v[0] += p0.x + q0.x; v[1] += p0.y + q0.y;
        v[2] += p0.z + q0.z; v[3] += p0.w + q0.w;
        v[4] += p1.x + q1.x; v[5] += p1.y + q1.y;
        v[6] += p1.z + q1.z; v[7] += p1.w + q1.w;
    }
    red4(&C[b*Dd + eo],     v[0], v[1], v[2], v[3]);
    red4(&C[b*Dd + eo + 4], v[4], v[5], v[6], v[7]);

    if (STAGE == 2 && blockIdx.y == 0) {
        // s[b] += dot(local ye2 contribution, w_proj[eo..eo+7])
        float4 wp0 = *(const float4*)&w_proj[eo];
        float4 wp1 = *(const float4*)&w_proj[eo + 4];
        float sp = v[0]*wp0.x + v[1]*wp0.y + v[2]*wp0.z + v[3]*wp0.w
                 + v[4]*wp1.x + v[5]*wp1.y + v[6]*wp1.z + v[7]*wp1.w;
        sp += __shfl_xor_sync(0xffffffffu, sp, 1);
        sp += __shfl_xor_sync(0xffffffffu, sp, 2);
        if (eg == 0) atomicAdd(&g_s_pad[b*32], sp);
    }
}

// ---------------------------------------------------------------------------
// K4: out[b,l] = s[b] * dot(zz2[b,:], W_zlat[l,:])
// CTA: 64b x 64l, 256 threads, thread 8b x 2l (8 FFMA2 accs).
// Both A (zz2, row-major, transposed in-smem) and W via LDG->STS, double
// buffered with register staging; single __syncthreads per chunk.
// ---------------------------------------------------------------------------
__global__ void __launch_bounds__(256) k_big(const float* __restrict__ Wz,
                                             float* __restrict__ out) {
    __shared__ float sA[2][32*68];   // [k][b] pad 68
    __shared__ float sW[2][32*65];   // [k][l] pad 65
    const int t  = threadIdx.x;
    const int l0 = blockIdx.x * 64;
    const int lc = t & 31;           // l = l0+lc, l0+32+lc
    const int bg = t >> 5;           // b = 4bg..4bg+3 and 32+4bg..+3

    float4 av[2], wv[2];
    auto ldg = [&](int c) {
        #pragma unroll
        for (int r = 0; r < 2; r++) {
            int id = t + 256*r;      // 0..511: row=id>>3 (64), k4=id&7 (8)
            int row = id >> 3, k4 = id & 7;
            av[r] = *(const float4*)(g_zz2 + row*Dd + c*32 + 4*k4);
            wv[r] = *(const float4*)(Wz + (l0 + row)*Dd + c*32 + 4*k4);
        }
    };
    auto sts = [&](int buf) {
        #pragma unroll
        for (int r = 0; r < 2; r++) {
            int id = t + 256*r;
            int row = id >> 3, k4 = id & 7;
            sA[buf][(4*k4 + 0)*68 + row] = av[r].x;
            sA[buf][(4*k4 + 1)*68 + row] = av[r].y;
            sA[buf][(4*k4 + 2)*68 + row] = av[r].z;
            sA[buf][(4*k4 + 3)*68 + row] = av[r].w;
            sW[buf][(4*k4 + 0)*65 + row] = wv[r].x;
            sW[buf][(4*k4 + 1)*65 + row] = wv[r].y;
            sW[buf][(4*k4 + 2)*65 + row] = wv[r].z;
            sW[buf][(4*k4 + 3)*65 + row] = wv[r].w;
        }
    };

    ull acc[4][2];
    #pragma unroll
    for (int i = 0; i < 4; i++) { acc[i][0] = 0; acc[i][1] = 0; }

    ldg(0);
    #pragma unroll 1
    for (int c = 0; c < 16; c++) {
        const int cur = c & 1;
        sts(cur);
        __syncthreads();             // cur visible; also fences prev-buf readers
        if (c < 15) ldg(c + 1);      // prefetch into regs (no smem writes)
        const float* Ab = sA[cur];
        const float* Wb = sW[cur];
        #pragma unroll 4
        for (int k = 0; k < 32; k++) {
            ulonglong2 a01 = *(const ulonglong2*)&Ab[k*68 + 4*bg];
            ulonglong2 a23 = *(const ulonglong2*)&Ab[k*68 + 32 + 4*bg];
            float w0 = Wb[k*65 + lc];
            float w1 = Wb[k*65 + 32 + lc];
            ull wp0 = pack2(w0, w0), wp1 = pack2(w1, w1);
            ffma2(acc[0][0], a01.x, wp0); ffma2(acc[1][0], a01.y, wp0);
            ffma2(acc[2][0], a23.x, wp0); ffma2(acc[3][0], a23.y, wp0);
            ffma2(acc[0][1], a01.x, wp1); ffma2(acc[1][1], a01.y, wp1);
            ffma2(acc[2][1], a23.x, wp1); ffma2(acc[3][1], a23.y, wp1);
        }
        __syncthreads();             // done reading cur before buf reuse (c+2)
    }

    // scale by s[b] and store
    int bb[4] = { 4*bg, 4*bg + 2, 32 + 4*bg, 32 + 4*bg + 2 };
    ull sp[4];
    #pragma unroll
    for (int p = 0; p < 4; p++)
        sp[p] = pack2(g_s_pad[bb[p]*32], g_s_pad[(bb[p] + 1)*32]);
    #pragma unroll
    for (int p = 0; p < 4; p++) {
        #pragma unroll
        for (int j = 0; j < 2; j++) {
            float lo, hi;
            unpack2(lo, hi, fmul2(acc[p][j], sp[p]));
            out[(bb[p] + 0)*Ll + l0 + 32*j + lc] = lo;
            out[(bb[p] + 1)*Ll + l0 + 32*j + lc] = hi;
        }
    }
}

extern "C" void kernel_launch(void* const* d_in, const int* in_sizes, int n_in,
                              void* d_out, int out_size) {
    const float* z      = (const float*)d_in[0];
    const int*   y      = (const int*)  d_in[1];
    const float* W_yemb = (const float*)d_in[2];
    const float* b_yemb = (const float*)d_in[3];
    const float* Wy1    = (const float*)d_in[4];
    const float* by1    = (const float*)d_in[5];
    const float* Wy2    = (const float*)d_in[6];
    const float* by2    = (const float*)d_in[7];
    const float* Wz1    = (const float*)d_in[8];
    const float* bz1    = (const float*)d_in[9];
    const float* Wz2    = (const float*)d_in[10];
    const float* bz2    = (const float*)d_in[11];
    const float* W_zlat = (const float*)d_in[12];
    const float* w_proj = (const float*)d_in[13];
    float* out = (float*)d_out;

    k_prep<<<dim3(Bsz, 4), 128>>>(z, y, W_yemb, b_yemb, by1, bz1);
    k_small<1><<<dim3(128, 2), 256>>>(z, Wy1, Wz1, nullptr, nullptr, nullptr);
    k_small<2><<<dim3(128, 2), 256>>>(z, Wy2, Wz2, by2, bz2, w_proj);
    k_big<<<Ll/64, 256>>>(W_zlat, out);
}

// round 6
// speedup vs baseline: 1.1542x; 1.0519x over previous
#include <cuda_runtime.h>

#define Bsz 64
#define Dd  512
#define Ll  8192
#define NLn 1000

typedef unsigned long long ull;

// Intermediates (device globals; allocations forbidden).
// Never passed as host-side kernel args — kernels reference them directly.
__device__ __align__(16) float g_ye0 [Bsz*Dd];
__device__ __align__(16) float g_ye1 [Bsz*Dd];
__device__ __align__(16) float g_ye2 [Bsz*Dd];
__device__ __align__(16) float g_zz1 [Bsz*Dd];
__device__ __align__(16) float g_zz2 [Bsz*Dd];
__device__ __align__(16) float g_s_pad[Bsz*32];   // s[b] at b*32 (sector-spread atomics)

__device__ __forceinline__ void cp_async16(void* dst, const void* src) {
    unsigned s = (unsigned)__cvta_generic_to_shared(dst);
    asm volatile("cp.async.cg.shared.global [%0], [%1], 16;" :: "r"(s), "l"(src) : "memory");
}
__device__ __forceinline__ ull pack2(float lo, float hi) {
    ull r; asm("mov.b64 %0, {%1, %2};" : "=l"(r) : "f"(lo), "f"(hi)); return r;
}
__device__ __forceinline__ void unpack2(float& lo, float& hi, ull v) {
    asm("mov.b64 {%0, %1}, %2;" : "=f"(lo), "=f"(hi) : "l"(v));
}
__device__ __forceinline__ void ffma2(ull& d, ull a, ull b) {
    asm("fma.rn.f32x2 %0, %1, %2, %0;" : "+l"(d) : "l"(a), "l"(b));
}
__device__ __forceinline__ ull fmul2(ull a, ull b) {
    ull r; asm("mul.rn.f32x2 %0, %1, %2;" : "=l"(r) : "l"(a), "l"(b)); return r;
}
__device__ __forceinline__ void red4(float* p, float v0, float v1, float v2, float v3) {
    asm volatile("red.global.add.v4.f32 [%0], {%1,%2,%3,%4};"
                 :: "l"(p), "f"(v0), "f"(v1), "f"(v2), "f"(v3) : "memory");
}

// ---------------------------------------------------------------------------
// K1: ye0 gather, stage-1 residual inits, zero stage-2 accumulators + s.
// ---------------------------------------------------------------------------
__global__ void k_prep(const float* __restrict__ z, const int* __restrict__ y,
                       const float* __restrict__ W_yemb, const float* __restrict__ b_yemb,
                       const float* __restrict__ by1, const float* __restrict__ bz1) {
    int b = blockIdx.x;
    int e = blockIdx.y * 128 + threadIdx.x;
    int yb = __ldg(y + b);
    float v  = __ldg(W_yemb + e*NLn + yb) + b_yemb[e];
    float zv = z[b*Dd + e];
    g_ye0[b*Dd + e] = v;
    g_ye1[b*Dd + e] = v  + by1[e];
    g_zz1[b*Dd + e] = zv + bz1[e];
    g_ye2[b*Dd + e] = 0.f;
    g_zz2[b*Dd + e] = 0.f;
    if (blockIdx.y == 0 && threadIdx.x == 0) g_s_pad[b*32] = 0.f;
}

// ---------------------------------------------------------------------------
// Small residual GEMM (unchanged from passing R5 kernel).
// ---------------------------------------------------------------------------
template<int STAGE>
__global__ void __launch_bounds__(256) k_small(const float* __restrict__ z,
                                               const float* __restrict__ Wy,
                                               const float* __restrict__ Wz,
                                               const float* __restrict__ b2y,
                                               const float* __restrict__ b2z,
                                               const float* __restrict__ w_proj) {
    __shared__ float sA[64*68];   // [b][k] pad 68 (broadcast-read conflict-free)
    __shared__ float sW[64*32];   // [k][e] transposed
    const float* A; const float* W; const float* b2; float* C;
    if (STAGE == 1) {
        if (blockIdx.y == 0) { A = g_ye0; W = Wy; b2 = nullptr; C = g_ye1; }
        else                 { A = z;     W = Wz; b2 = nullptr; C = g_zz1; }
    } else {
        if (blockIdx.y == 0) { A = g_ye1; W = Wy; b2 = b2y; C = g_ye2; }
        else                 { A = g_zz1; W = Wz; b2 = b2z; C = g_zz2; }
    }
    const int t  = threadIdx.x;
    const int e0 = (blockIdx.x & 15) * 32;
    const int k0 = (blockIdx.x >> 4) * 64;

    #pragma unroll
    for (int r = 0; r < 4; r++) {
        int id = t + 256*r;              // 0..1023
        int b = id >> 4, k4 = id & 15;
        cp_async16(&sA[b*68 + 4*k4], A + b*Dd + k0 + 4*k4);
    }
    asm volatile("cp.async.commit_group;" ::: "memory");
    float4 wv[2]; int we[2], wk[2];
    #pragma unroll
    for (int r = 0; r < 2; r++) {
        int id = t + 256*r;              // 0..511
        we[r] = id >> 4; wk[r] = id & 15;
        wv[r] = *(const float4*)(W + (e0 + we[r])*Dd + k0 + 4*wk[r]);
    }
    #pragma unroll
    for (int r = 0; r < 2; r++) {
        sW[(4*wk[r] + 0)*32 + we[r]] = wv[r].x;
        sW[(4*wk[r] + 1)*32 + we[r]] = wv[r].y;
        sW[(4*wk[r] + 2)*32 + we[r]] = wv[r].z;
        sW[(4*wk[r] + 3)*32 + we[r]] = wv[r].w;
    }
    asm volatile("cp.async.wait_group 0;" ::: "memory");
    __syncthreads();

    const int b  = t >> 2;     // 0..63
    const int eg = t & 3;      // e-octet: e0 + eg*8 .. +7
    ull acc[4] = {0, 0, 0, 0};

    #pragma unroll 8
    for (int k = 0; k < 64; k++) {
        float a = sA[b*68 + k];
        ull ap = pack2(a, a);
        ulonglong2 wA = *(const ulonglong2*)&sW[k*32 + eg*8];
        ulonglong2 wB = *(const ulonglong2*)&sW[k*32 + eg*8 + 4];
        ffma2(acc[0], ap, wA.x);
        ffma2(acc[1], ap, wA.y);
        ffma2(acc[2], ap, wB.x);
        ffma2(acc[3], ap, wB.y);
    }

    float v[8];
    unpack2(v[0], v[1], acc[0]);
    unpack2(v[2], v[3], acc[1]);
    unpack2(v[4], v[5], acc[2]);
    unpack2(v[6], v[7], acc[3]);
    const int eo = e0 + eg*8;
    if (STAGE == 2 && k0 == 0) {
        float4 p0 = *(const float4*)&A[b*Dd + eo];
        float4 p1 = *(const float4*)&A[b*Dd + eo + 4];
        float4 q0 = *(const float4*)&b2[eo];
        float4 q1 = *(const float4*)&b2[eo + 4];
        v[0] += p0.x + q0.x; v[1] += p0.y + q0.y;
        v[2] += p0.z + q0.z; v[3] += p0.w + q0.w;
        v[4] += p1.x + q1.x; v[5] += p1.y + q1.y;
        v[6] += p1.z + q1.z; v[7] += p1.w + q1.w;
    }
    red4(&C[b*Dd + eo],     v[0], v[1], v[2], v[3]);
    red4(&C[b*Dd + eo + 4], v[4], v[5], v[6], v[7]);

    if (STAGE == 2 && blockIdx.y == 0) {
        float4 wp0 = *(const float4*)&w_proj[eo];
        float4 wp1 = *(const float4*)&w_proj[eo + 4];
        float sp = v[0]*wp0.x + v[1]*wp0.y + v[2]*wp0.z + v[3]*wp0.w
                 + v[4]*wp1.x + v[5]*wp1.y + v[6]*wp1.z + v[7]*wp1.w;
        sp += __shfl_xor_sync(0xffffffffu, sp, 1);
        sp += __shfl_xor_sync(0xffffffffu, sp, 2);
        if (eg == 0) atomicAdd(&g_s_pad[b*32], sp);
    }
}

// ---------------------------------------------------------------------------
// K4: out[b,l] = s[b] * dot(zz2[b,:], W_zlat[l,:])
// K-PAIRED FFMA2: acc[b][l] holds (even-k, odd-k) partial sums; both A and W
// are consumed as row-major LDS.128 (4 k at a time) -> NO transposes, NO packs,
// pure cp.async producer. CTA 64b x 64l, 256 threads, thread tile 4b x 4l.
// Per warp per 4k: 4 a-LDS.128 (1 wf) + 4 w-LDS.128 (2 wf) = 12 wf;
// 24 wf/k/CTA < 32 fma-cyc/k -> fma-bound.
// ---------------------------------------------------------------------------
#define KCH 32            // k per chunk
#define SSTR 36           // row stride (32 + 4 pad), 144B = 16B-aligned
__global__ void __launch_bounds__(256) k_big(const float* __restrict__ Wz,
                                             float* __restrict__ out) {
    __shared__ float sA[2][64*SSTR];   // [b][k] row-major
    __shared__ float sW[2][64*SSTR];   // [l][k] row-major
    const int t    = threadIdx.x;
    const int l0   = blockIdx.x * 64;
    const int lgrp = t & 15;           // l = l0 + lgrp + 16j
    const int bgrp = t >> 4;           // b = 4*bgrp + i   (0..15)

    auto load = [&](int buf, int c) {
        #pragma unroll
        for (int r = 0; r < 2; r++) {
            int id  = t + 256*r;       // 0..511
            int row = id >> 3, k4 = id & 7;
            cp_async16(&sA[buf][row*SSTR + 4*k4], g_zz2 + row*Dd + c*KCH + 4*k4);
            cp_async16(&sW[buf][row*SSTR + 4*k4], Wz + (l0 + row)*Dd + c*KCH + 4*k4);
        }
        asm volatile("cp.async.commit_group;" ::: "memory");
    };

    ull acc[4][4];
    #pragma unroll
    for (int i = 0; i < 4; i++)
        #pragma unroll
        for (int j = 0; j < 4; j++) acc[i][j] = 0;

    load(0, 0);
    #pragma unroll 1
    for (int c = 0; c < 16; c++) {
        const int cur = c & 1;
        asm volatile("cp.async.wait_group 0;" ::: "memory");  // chunk c arrived
        __syncthreads();               // all arrived; prior reads of other buf done
        if (c < 15) load(cur ^ 1, c + 1);   // prefetch overlaps compute
        const float* Ab = sA[cur];
        const float* Wb = sW[cur];
        #pragma unroll
        for (int kk = 0; kk < KCH/4; kk++) {
            ulonglong2 a[4], w[4];
            #pragma unroll
            for (int i = 0; i < 4; i++)
                a[i] = *(const ulonglong2*)&Ab[(4*bgrp + i)*SSTR + 4*kk];
            #pragma unroll
            for (int j = 0; j < 4; j++)
                w[j] = *(const ulonglong2*)&Wb[(lgrp + 16*j)*SSTR + 4*kk];
            #pragma unroll
            for (int i = 0; i < 4; i++)
                #pragma unroll
                for (int j = 0; j < 4; j++) {
                    ffma2(acc[i][j], a[i].x, w[j].x);
                    ffma2(acc[i][j], a[i].y, w[j].y);
                }
        }
    }

    // reduce k-pairs, scale by s[b], store
    #pragma unroll
    for (int i = 0; i < 4; i++) {
        const int b = 4*bgrp + i;
        const float s = g_s_pad[b*32];
        #pragma unroll
        for (int j = 0; j < 4; j++) {
            float lo, hi;
            unpack2(lo, hi, acc[i][j]);
            out[b*Ll + l0 + lgrp + 16*j] = (lo + hi) * s;
        }
    }
}

extern "C" void kernel_launch(void* const* d_in, const int* in_sizes, int n_in,
                              void* d_out, int out_size) {
    const float* z      = (const float*)d_in[0];
    const int*   y      = (const int*)  d_in[1];
    const float* W_yemb = (const float*)d_in[2];
    const float* b_yemb = (const float*)d_in[3];
    const float* Wy1    = (const float*)d_in[4];
    const float* by1    = (const float*)d_in[5];
    const float* Wy2    = (const float*)d_in[6];
    const float* by2    = (const float*)d_in[7];
    const float* Wz1    = (const float*)d_in[8];
    const float* bz1    = (const float*)d_in[9];
    const float* Wz2    = (const float*)d_in[10];
    const float* bz2    = (const float*)d_in[11];
    const float* W_zlat = (const float*)d_in[12];
    const float* w_proj = (const float*)d_in[13];
    float* out = (float*)d_out;

    k_prep<<<dim3(Bsz, 4), 128>>>(z, y, W_yemb, b_yemb, by1, bz1);
    k_small<1><<<dim3(128, 2), 256>>>(z, Wy1, Wz1, nullptr, nullptr, nullptr);
    k_small<2><<<dim3(128, 2), 256>>>(z, Wy2, Wz2, by2, bz2, w_proj);
    k_big<<<Ll/64, 256>>>(W_zlat, out);
}